// round 13
// baseline (speedup 1.0000x reference)
#include <cuda_runtime.h>
#include <cuda_fp16.h>
#include <cstdint>

#define NB 8
#define NC 64
#define NPTS 65536
#define RR 32
#define R3 32768
#define TILE 128          // voxelize tile
#define DT 64             // devox tile
#define INVN (1.0f / 65536.0f)

// ---------------- device scratch ----------------
__device__ __half g_voxh[(size_t)NB * R3 * NC];   // fp16 voxel SUMS, [b][voxel][c]
__device__ float  g_cnt [NB * R3];                // per-voxel point counts
__device__ float  g_stats[2 * NB * 4];            // [t][b]{sumx,sumy,sumz, maxsq}

// ---------------- stats pass 1: partial axis sums + fused scratch zeroing ----------------
__global__ void __launch_bounds__(256) k_sum(const float* __restrict__ c1,
                                             const float* __restrict__ c2) {
    int blk = blockIdx.x;           // 128 blocks: t(1) | b(3) | chunk(3)
    int t = blk >> 6, b = (blk >> 3) & 7, ch = blk & 7;
    const float* cb = (t ? c2 : c1) + (size_t)b * 3 * NPTS;
    const int CH = NPTS / 8;
    const float4* px = (const float4*)(cb + ch * CH);
    const float4* py = (const float4*)(cb + NPTS + ch * CH);
    const float4* pz = (const float4*)(cb + 2 * NPTS + ch * CH);

    float sx = 0.f, sy = 0.f, sz = 0.f;
    for (int i = threadIdx.x; i < CH / 4; i += 256) {
        float4 a = px[i]; sx += (a.x + a.y) + (a.z + a.w);
        float4 c = py[i]; sy += (c.x + c.y) + (c.z + c.w);
        float4 e = pz[i]; sz += (e.x + e.y) + (e.z + e.w);
    }
    #pragma unroll
    for (int o = 16; o > 0; o >>= 1) {
        sx += __shfl_down_sync(0xffffffffu, sx, o);
        sy += __shfl_down_sync(0xffffffffu, sy, o);
        sz += __shfl_down_sync(0xffffffffu, sz, o);
    }
    __shared__ float rs[8][3];
    if ((threadIdx.x & 31) == 0) {
        int w = threadIdx.x >> 5;
        rs[w][0] = sx; rs[w][1] = sy; rs[w][2] = sz;
    }
    __syncthreads();
    if (threadIdx.x < 3) {
        float s = 0.f;
        #pragma unroll
        for (int w = 0; w < 8; w++) s += rs[w][threadIdx.x];
        atomicAdd(&g_stats[(t * NB + b) * 4 + threadIdx.x], s);
    }

    // fused zeroing of voxel grid + counts (grid-strided uint4 stores)
    {
        const uint4 z = make_uint4(0u, 0u, 0u, 0u);
        size_t gtid = (size_t)blk * 256 + threadIdx.x;       // 32768 threads
        uint4* vz = (uint4*)g_voxh;                          // 33.5MB = 2.097M uint4
        const size_t NV = (size_t)NB * R3 * NC / 8;
        for (size_t i = gtid; i < NV; i += 32768) vz[i] = z;
        uint4* cz = (uint4*)g_cnt;                           // 1MB = 65536 uint4
        const size_t NCNT = (size_t)NB * R3 / 4;
        for (size_t i = gtid; i < NCNT; i += 32768) cz[i] = z;
    }
}

// ---------------- stats pass 2: max squared centered norm via atomicMax ----------------
__global__ void __launch_bounds__(256) k_maxsq(const float* __restrict__ c1,
                                               const float* __restrict__ c2) {
    int blk = blockIdx.x;
    int t = blk >> 6, b = (blk >> 3) & 7, ch = blk & 7;
    const float* cb = (t ? c2 : c1) + (size_t)b * 3 * NPTS;
    const float* st = &g_stats[(t * NB + b) * 4];
    float mx = st[0] * INVN, my = st[1] * INVN, mz = st[2] * INVN;

    const int CH = NPTS / 8;
    const float4* px = (const float4*)(cb + ch * CH);
    const float4* py = (const float4*)(cb + NPTS + ch * CH);
    const float4* pz = (const float4*)(cb + 2 * NPTS + ch * CH);

    float mm = 0.f;
    for (int i = threadIdx.x; i < CH / 4; i += 256) {
        float4 a = px[i], c = py[i], e = pz[i];
        float dx, dy, dz;
        dx = a.x - mx; dy = c.x - my; dz = e.x - mz; mm = fmaxf(mm, dx*dx + dy*dy + dz*dz);
        dx = a.y - mx; dy = c.y - my; dz = e.y - mz; mm = fmaxf(mm, dx*dx + dy*dy + dz*dz);
        dx = a.z - mx; dy = c.z - my; dz = e.z - mz; mm = fmaxf(mm, dx*dx + dy*dy + dz*dz);
        dx = a.w - mx; dy = c.w - my; dz = e.w - mz; mm = fmaxf(mm, dx*dx + dy*dy + dz*dz);
    }
    #pragma unroll
    for (int o = 16; o > 0; o >>= 1)
        mm = fmaxf(mm, __shfl_down_sync(0xffffffffu, mm, o));
    __shared__ float rs[8];
    if ((threadIdx.x & 31) == 0) rs[threadIdx.x >> 5] = mm;
    __syncthreads();
    if (threadIdx.x == 0) {
        float m = 0.f;
        #pragma unroll
        for (int w = 0; w < 8; w++) m = fmaxf(m, rs[w]);
        atomicMax((unsigned*)&g_stats[(t * NB + b) * 4 + 3], __float_as_uint(m));
    }
}

__device__ __forceinline__ float norm1(float v, float mean, float scale) {
    float x = ((v - mean) / scale + 0.5f) * (float)RR;
    return fminf(fmaxf(x, 0.0f), (float)(RR - 1));
}

// ---------------- voxelize batch b + copy x1f channels [0,32) of batch b ----------------
__global__ void __launch_bounds__(256) k_vox(const float* __restrict__ feat,
                                             const float* __restrict__ coords,
                                             const float* __restrict__ x1f,
                                             float* __restrict__ out, int b) {
    int n0 = blockIdx.x * TILE;
    int tid = threadIdx.x;

    __shared__ float sfeat[TILE][68];
    __shared__ int   sidx[TILE];

    if (tid < TILE) {
        int n = n0 + tid;
        const float* cb = coords + (size_t)b * 3 * NPTS;
        const float* st = &g_stats[(1 * NB + b) * 4];
        float sc = 2.0f * sqrtf(st[3]);
        float nx = norm1(cb[n],            st[0] * INVN, sc);
        float ny = norm1(cb[NPTS + n],     st[1] * INVN, sc);
        float nz = norm1(cb[2 * NPTS + n], st[2] * INVN, sc);
        int vi = (((int)rintf(nx)) * RR + (int)rintf(ny)) * RR + (int)rintf(nz);
        sidx[tid] = vi;
        atomicAdd(&g_cnt[b * R3 + vi], 1.0f);
    }

    // coalesced scalar feature load, transposed into smem (point-major, conflict-free STS)
    {
        int nl = tid & 127;
        for (int c = tid >> 7; c < NC; c += 2)
            sfeat[nl][c] = feat[((size_t)b * NC + c) * NPTS + n0 + nl];
    }

    // fused half-copy: x1_features channels [0,32) -> out
    {
        const float4* src = (const float4*)(x1f + (size_t)b * NC * NPTS);
        float4*       dst = (float4*)(out + (size_t)b * 2 * NC * NPTS);
        int g0 = n0 >> 2;
        for (int i = tid; i < 32 * (TILE / 4); i += 256) {   // 1024 float4, 4/thread
            int c = i >> 5, g = i & 31;
            size_t off = (size_t)c * (NPTS / 4) + g0 + g;
            dst[off] = src[off];
        }
    }
    __syncthreads();

    // scatter: 8 fp16x8 vector reductions per point (128B/point, one line)
    __half* vbase = g_voxh + (size_t)b * R3 * NC;
    for (int i = tid; i < TILE * 8; i += 256) {
        int nl = i >> 3;
        int c8 = i & 7;
        const float4* row = (const float4*)&sfeat[nl][c8 * 8];
        float4 a = row[0], c = row[1];
        __half2 p0 = __floats2half2_rn(a.x, a.y);
        __half2 p1 = __floats2half2_rn(a.z, a.w);
        __half2 p2 = __floats2half2_rn(c.x, c.y);
        __half2 p3 = __floats2half2_rn(c.z, c.w);
        __half* addr = vbase + (size_t)sidx[nl] * NC + c8 * 8;
        asm volatile("red.global.add.noftz.v4.f16x2 [%0], {%1,%2,%3,%4};"
                     :: "l"(addr),
                        "r"(*(unsigned*)&p0), "r"(*(unsigned*)&p1),
                        "r"(*(unsigned*)&p2), "r"(*(unsigned*)&p3) : "memory");
    }
}

// ---------------- devoxelize batch b + copy x1f channels [32,64) of batch b ----------------
__global__ void __launch_bounds__(256, 8) k_devox(const float* __restrict__ x1f,
                                                  const float* __restrict__ x1c,
                                                  float* __restrict__ out, int b) {
    int n0 = blockIdx.x * DT;
    int tid = threadIdx.x;

    __shared__ float sout[DT][65];      // odd stride
    __shared__ uint2 sow[DT][8];        // {voxel idx, half2(w,w)}

    // Phase A: copy x1_features channels [32,64) -> out
    {
        const float4* src = (const float4*)(x1f + (size_t)b * NC * NPTS);
        float4*       dst = (float4*)(out + (size_t)b * 2 * NC * NPTS);
        int g0 = n0 >> 2;
        for (int i = tid; i < 32 * (DT / 4); i += 256) {     // 512 float4, 2/thread
            int c = 32 + (i >> 4), g = i & 15;
            size_t off = (size_t)c * (NPTS / 4) + g0 + g;
            dst[off] = src[off];
        }
    }

    // Phase B: trilinear corners + fp16 weights (count division folded in)
    if (tid < DT) {
        int n = n0 + tid;
        const float* cb = x1c + (size_t)b * 3 * NPTS;
        const float* st = &g_stats[(0 * NB + b) * 4];
        float sc = 2.0f * sqrtf(st[3]);
        float nx = norm1(cb[n],            st[0] * INVN, sc);
        float ny = norm1(cb[NPTS + n],     st[1] * INVN, sc);
        float nz = norm1(cb[2 * NPTS + n], st[2] * INVN, sc);

        float lx = floorf(nx), ly = floorf(ny), lz = floorf(nz);
        float dx = nx - lx,    dy = ny - ly,    dz = nz - lz;
        int ix = (int)lx, iy = (int)ly, iz = (int)lz;
        int hx = min(ix + 1, RR - 1), hy = min(iy + 1, RR - 1), hz = min(iz + 1, RR - 1);

        int   cx[2] = {ix, hx},       cy[2] = {iy, hy},       cz[2] = {iz, hz};
        float wx[2] = {1.f - dx, dx}, wy[2] = {1.f - dy, dy}, wz[2] = {1.f - dz, dz};

        const float* cnt = g_cnt + b * R3;
        #pragma unroll
        for (int k = 0; k < 8; k++) {
            int a = k >> 2, bb = (k >> 1) & 1, cc = k & 1;
            int idx = (cx[a] * RR + cy[bb]) * RR + cz[cc];
            float w = __fdividef(wx[a] * wy[bb] * wz[cc], fmaxf(__ldg(&cnt[idx]), 1.0f));
            __half2 wh = __floats2half2_rn(w, w);
            sow[tid][k] = make_uint2((unsigned)idx, *reinterpret_cast<unsigned*>(&wh));
        }
    }
    __syncthreads();

    // Phase C: HFMA2 gather (8 lanes x 16B cover one corner's 64 channels)
    {
        const uint4* vb = (const uint4*)(g_voxh + (size_t)b * R3 * NC);
        for (int i = tid; i < DT * 8; i += 256) {            // 512 items, 2/thread
            int nl = i >> 3;
            int c8 = i & 7;
            __half2 h0 = __float2half2_rn(0.f), h1 = h0, h2 = h0, h3 = h0;
            #pragma unroll
            for (int k = 0; k < 8; k++) {
                uint2 e = sow[nl][k];
                __half2 wh = *reinterpret_cast<__half2*>(&e.y);
                uint4 v = vb[(size_t)e.x * (NC / 8) + c8];
                const __half2* hp = (const __half2*)&v;
                h0 = __hfma2(hp[0], wh, h0);
                h1 = __hfma2(hp[1], wh, h1);
                h2 = __hfma2(hp[2], wh, h2);
                h3 = __hfma2(hp[3], wh, h3);
            }
            float2 f0 = __half22float2(h0);
            float2 f1 = __half22float2(h1);
            float2 f2 = __half22float2(h2);
            float2 f3 = __half22float2(h3);
            int c = c8 * 8;
            sout[nl][c + 0] = f0.x; sout[nl][c + 1] = f0.y;
            sout[nl][c + 2] = f1.x; sout[nl][c + 3] = f1.y;
            sout[nl][c + 4] = f2.x; sout[nl][c + 5] = f2.y;
            sout[nl][c + 6] = f3.x; sout[nl][c + 7] = f3.y;
        }
    }
    __syncthreads();

    // Phase D: transpose -> out channels [64,128), float4 stores along N
    {
        float* dsto = out + ((size_t)b * 2 * NC + NC) * NPTS;
        for (int i = tid; i < NC * (DT / 4); i += 256) {     // 1024 float4, 4/thread
            int c = i >> 4, g = i & 15;
            int nl = g * 4;
            float4 v = make_float4(sout[nl][c], sout[nl + 1][c],
                                   sout[nl + 2][c], sout[nl + 3][c]);
            *(float4*)&dsto[(size_t)c * NPTS + n0 + nl] = v;
        }
    }
}

// ---------------- launch: per-batch vox->devox pipelined across two streams ----------------
// Side stream + events are function-local statics: created once on the FIRST call
// (the correctness run, before the harness's pre-capture memory baseline), reused
// on every subsequent call including capture. Nothing is created or destroyed
// during capture, and post-teardown memory matches the baseline.
extern "C" void kernel_launch(void* const* d_in, const int* in_sizes, int n_in,
                              void* d_out, int out_size) {
    const float* fptr[2] = {nullptr, nullptr};
    const float* cptr[2] = {nullptr, nullptr};
    int fi = 0, ci = 0;
    for (int i = 0; i < 4; i++) {
        if (in_sizes[i] == NB * NC * NPTS) { if (fi < 2) fptr[fi++] = (const float*)d_in[i]; }
        else                               { if (ci < 2) cptr[ci++] = (const float*)d_in[i]; }
    }
    const float* x1f = fptr[0];
    const float* x2f = fptr[1];
    const float* x1c = cptr[0];
    const float* x2c = cptr[1];
    float* out = (float*)d_out;

    static cudaStream_t s2 = nullptr;
    static cudaEvent_t  ev[NB + 1];
    if (s2 == nullptr) {
        cudaStreamCreateWithFlags(&s2, cudaStreamNonBlocking);
        for (int i = 0; i <= NB; i++)
            cudaEventCreateWithFlags(&ev[i], cudaEventDisableTiming);
    }

    void* stats_ptr = nullptr;
    cudaGetSymbolAddress(&stats_ptr, g_stats);
    cudaMemsetAsync(stats_ptr, 0, 2 * NB * 4 * sizeof(float));

    k_sum<<<128, 256>>>(x1c, x2c);      // also zeroes g_voxh + g_cnt
    k_maxsq<<<128, 256>>>(x1c, x2c);

    // pipeline: vox(b) on main stream, devox(b) on side stream gated by ev[b]
    for (int b = 0; b < NB; b++) {
        k_vox<<<NPTS / TILE, 256>>>(x2f, x2c, x1f, out, b);
        cudaEventRecord(ev[b], 0);
        cudaStreamWaitEvent(s2, ev[b], 0);
        k_devox<<<NPTS / DT, 256, 0, s2>>>(x1f, x1c, out, b);
    }

    // join side stream back into the main (captured) stream
    cudaEventRecord(ev[NB], s2);
    cudaStreamWaitEvent(0, ev[NB], 0);
}

// round 15
// speedup vs baseline: 1.3817x; 1.3817x over previous
#include <cuda_runtime.h>
#include <cuda_fp16.h>
#include <cstdint>

#define NB 8
#define NC 64
#define NPTS 65536
#define RR 32
#define R3 32768
#define DT 64             // devox tile
#define INVN (1.0f / 65536.0f)

// ---------------- device scratch ----------------
__device__ __half g_voxh[(size_t)NB * R3 * NC];   // fp16 voxel SUMS, [b][voxel][c]
__device__ float  g_cnt [NB * R3];                // per-voxel point counts
__device__ float  g_stats[2 * NB * 4];            // [t][b]{sumx,sumy,sumz, maxsq}

// ---------------- stats pass 1: partial axis sums + fused scratch zeroing ----------------
__global__ void __launch_bounds__(256) k_sum(const float* __restrict__ c1,
                                             const float* __restrict__ c2) {
    int blk = blockIdx.x;           // 128 blocks: t(1) | b(3) | chunk(3)
    int t = blk >> 6, b = (blk >> 3) & 7, ch = blk & 7;
    const float* cb = (t ? c2 : c1) + (size_t)b * 3 * NPTS;
    const int CH = NPTS / 8;
    const float4* px = (const float4*)(cb + ch * CH);
    const float4* py = (const float4*)(cb + NPTS + ch * CH);
    const float4* pz = (const float4*)(cb + 2 * NPTS + ch * CH);

    float sx = 0.f, sy = 0.f, sz = 0.f;
    for (int i = threadIdx.x; i < CH / 4; i += 256) {
        float4 a = px[i]; sx += (a.x + a.y) + (a.z + a.w);
        float4 c = py[i]; sy += (c.x + c.y) + (c.z + c.w);
        float4 e = pz[i]; sz += (e.x + e.y) + (e.z + e.w);
    }
    #pragma unroll
    for (int o = 16; o > 0; o >>= 1) {
        sx += __shfl_down_sync(0xffffffffu, sx, o);
        sy += __shfl_down_sync(0xffffffffu, sy, o);
        sz += __shfl_down_sync(0xffffffffu, sz, o);
    }
    __shared__ float rs[8][3];
    if ((threadIdx.x & 31) == 0) {
        int w = threadIdx.x >> 5;
        rs[w][0] = sx; rs[w][1] = sy; rs[w][2] = sz;
    }
    __syncthreads();
    if (threadIdx.x < 3) {
        float s = 0.f;
        #pragma unroll
        for (int w = 0; w < 8; w++) s += rs[w][threadIdx.x];
        atomicAdd(&g_stats[(t * NB + b) * 4 + threadIdx.x], s);
    }

    // fused zeroing of voxel grid + counts (grid-strided uint4 stores)
    {
        const uint4 z = make_uint4(0u, 0u, 0u, 0u);
        size_t gtid = (size_t)blk * 256 + threadIdx.x;       // 32768 threads
        uint4* vz = (uint4*)g_voxh;                          // 33.5MB = 2.097M uint4
        const size_t NV = (size_t)NB * R3 * NC / 8;
        for (size_t i = gtid; i < NV; i += 32768) vz[i] = z;
        uint4* cz = (uint4*)g_cnt;                           // 1MB = 65536 uint4
        const size_t NCNT = (size_t)NB * R3 / 4;
        for (size_t i = gtid; i < NCNT; i += 32768) cz[i] = z;
    }
}

// ---------------- stats pass 2: max squared centered norm via atomicMax ----------------
__global__ void __launch_bounds__(256) k_maxsq(const float* __restrict__ c1,
                                               const float* __restrict__ c2) {
    int blk = blockIdx.x;
    int t = blk >> 6, b = (blk >> 3) & 7, ch = blk & 7;
    const float* cb = (t ? c2 : c1) + (size_t)b * 3 * NPTS;
    const float* st = &g_stats[(t * NB + b) * 4];
    float mx = st[0] * INVN, my = st[1] * INVN, mz = st[2] * INVN;

    const int CH = NPTS / 8;
    const float4* px = (const float4*)(cb + ch * CH);
    const float4* py = (const float4*)(cb + NPTS + ch * CH);
    const float4* pz = (const float4*)(cb + 2 * NPTS + ch * CH);

    float mm = 0.f;
    for (int i = threadIdx.x; i < CH / 4; i += 256) {
        float4 a = px[i], c = py[i], e = pz[i];
        float dx, dy, dz;
        dx = a.x - mx; dy = c.x - my; dz = e.x - mz; mm = fmaxf(mm, dx*dx + dy*dy + dz*dz);
        dx = a.y - mx; dy = c.y - my; dz = e.y - mz; mm = fmaxf(mm, dx*dx + dy*dy + dz*dz);
        dx = a.z - mx; dy = c.z - my; dz = e.z - mz; mm = fmaxf(mm, dx*dx + dy*dy + dz*dz);
        dx = a.w - mx; dy = c.w - my; dz = e.w - mz; mm = fmaxf(mm, dx*dx + dy*dy + dz*dz);
    }
    #pragma unroll
    for (int o = 16; o > 0; o >>= 1)
        mm = fmaxf(mm, __shfl_down_sync(0xffffffffu, mm, o));
    __shared__ float rs[8];
    if ((threadIdx.x & 31) == 0) rs[threadIdx.x >> 5] = mm;
    __syncthreads();
    if (threadIdx.x == 0) {
        float m = 0.f;
        #pragma unroll
        for (int w = 0; w < 8; w++) m = fmaxf(m, rs[w]);
        atomicMax((unsigned*)&g_stats[(t * NB + b) * 4 + 3], __float_as_uint(m));
    }
}

__device__ __forceinline__ float norm1(float v, float mean, float scale) {
    float x = ((v - mean) / scale + 0.5f) * (float)RR;
    return fminf(fmaxf(x, 0.0f), (float)(RR - 1));
}

// ---------------- voxelize x2: register-direct fp16 reds (no smem) + copy [0,32) ----------------
// Block = 256 threads covering 32 points x 8 channel-octets. Warp w handles
// channels [8w, 8w+8) for 32 consecutive points (lane = point). All feature
// LDGs coalesced; voxel index recomputed per warp (broadcast L1 hits).
__global__ void __launch_bounds__(256) k_vox(const float* __restrict__ feat,
                                             const float* __restrict__ coords,
                                             const float* __restrict__ x1f,
                                             float* __restrict__ out) {
    int b    = blockIdx.y;
    int n0   = blockIdx.x * 32;
    int tid  = threadIdx.x;
    int w    = tid >> 5;          // channel octet 0..7
    int lane = tid & 31;
    int n    = n0 + lane;

    // per-lane voxel index
    const float* cb = coords + (size_t)b * 3 * NPTS;
    const float* st = &g_stats[(1 * NB + b) * 4];
    float sc = 2.0f * sqrtf(st[3]);
    float nx = norm1(cb[n],            st[0] * INVN, sc);
    float ny = norm1(cb[NPTS + n],     st[1] * INVN, sc);
    float nz = norm1(cb[2 * NPTS + n], st[2] * INVN, sc);
    int vi = (((int)rintf(nx)) * RR + (int)rintf(ny)) * RR + (int)rintf(nz);
    if (w == 0) atomicAdd(&g_cnt[b * R3 + vi], 1.0f);

    // fused half-copy: x1_features channels [0,32) for points [n0, n0+32)
    {
        const float4* src = (const float4*)(x1f + (size_t)b * NC * NPTS);
        float4*       dst = (float4*)(out + (size_t)b * 2 * NC * NPTS);
        int c = tid >> 3;          // 0..31
        int g = tid & 7;           // 8 float4 = 32 floats
        size_t off = (size_t)c * (NPTS / 4) + (n0 >> 2) + g;
        dst[off] = src[off];
    }

    // 8 coalesced feature loads -> fp16 pack -> one vector reduction
    const float* fb = feat + ((size_t)b * NC + w * 8) * NPTS + n;
    float f0 = fb[0];
    float f1 = fb[NPTS];
    float f2 = fb[2 * NPTS];
    float f3 = fb[3 * NPTS];
    float f4 = fb[4 * NPTS];
    float f5 = fb[5 * NPTS];
    float f6 = fb[6 * NPTS];
    float f7 = fb[7 * NPTS];
    __half2 p0 = __floats2half2_rn(f0, f1);
    __half2 p1 = __floats2half2_rn(f2, f3);
    __half2 p2 = __floats2half2_rn(f4, f5);
    __half2 p3 = __floats2half2_rn(f6, f7);
    __half* addr = g_voxh + (size_t)b * R3 * NC + (size_t)vi * NC + w * 8;
    asm volatile("red.global.add.noftz.v4.f16x2 [%0], {%1,%2,%3,%4};"
                 :: "l"(addr),
                    "r"(*(unsigned*)&p0), "r"(*(unsigned*)&p1),
                    "r"(*(unsigned*)&p2), "r"(*(unsigned*)&p3) : "memory");
}

// ---------------- devoxelize + copy x1f channels [32,64): HFMA2 gather ----------------
__global__ void __launch_bounds__(256, 8) k_devox(const float* __restrict__ x1f,
                                                  const float* __restrict__ x1c,
                                                  float* __restrict__ out) {
    int b  = blockIdx.y;
    int n0 = blockIdx.x * DT;
    int tid = threadIdx.x;

    __shared__ float sout[DT][65];      // odd stride
    __shared__ uint2 sow[DT][8];        // {voxel idx, half2(w,w)}

    // Phase A: copy x1_features channels [32,64) -> out
    {
        const float4* src = (const float4*)(x1f + (size_t)b * NC * NPTS);
        float4*       dst = (float4*)(out + (size_t)b * 2 * NC * NPTS);
        int g0 = n0 >> 2;
        for (int i = tid; i < 32 * (DT / 4); i += 256) {     // 512 float4, 2/thread
            int c = 32 + (i >> 4), g = i & 15;
            size_t off = (size_t)c * (NPTS / 4) + g0 + g;
            dst[off] = src[off];
        }
    }

    // Phase B: trilinear corners + fp16 weights (count division folded in)
    if (tid < DT) {
        int n = n0 + tid;
        const float* cb = x1c + (size_t)b * 3 * NPTS;
        const float* st = &g_stats[(0 * NB + b) * 4];
        float sc = 2.0f * sqrtf(st[3]);
        float nx = norm1(cb[n],            st[0] * INVN, sc);
        float ny = norm1(cb[NPTS + n],     st[1] * INVN, sc);
        float nz = norm1(cb[2 * NPTS + n], st[2] * INVN, sc);

        float lx = floorf(nx), ly = floorf(ny), lz = floorf(nz);
        float dx = nx - lx,    dy = ny - ly,    dz = nz - lz;
        int ix = (int)lx, iy = (int)ly, iz = (int)lz;
        int hx = min(ix + 1, RR - 1), hy = min(iy + 1, RR - 1), hz = min(iz + 1, RR - 1);

        int   cx[2] = {ix, hx},       cy[2] = {iy, hy},       cz[2] = {iz, hz};
        float wx[2] = {1.f - dx, dx}, wy[2] = {1.f - dy, dy}, wz[2] = {1.f - dz, dz};

        const float* cnt = g_cnt + b * R3;
        #pragma unroll
        for (int k = 0; k < 8; k++) {
            int a = k >> 2, bb = (k >> 1) & 1, cc = k & 1;
            int idx = (cx[a] * RR + cy[bb]) * RR + cz[cc];
            float w = __fdividef(wx[a] * wy[bb] * wz[cc], fmaxf(__ldg(&cnt[idx]), 1.0f));
            __half2 wh = __floats2half2_rn(w, w);
            sow[tid][k] = make_uint2((unsigned)idx, *reinterpret_cast<unsigned*>(&wh));
        }
    }
    __syncthreads();

    // Phase C: HFMA2 gather (8 lanes x 16B cover one corner's 64 channels)
    {
        const uint4* vb = (const uint4*)(g_voxh + (size_t)b * R3 * NC);
        for (int i = tid; i < DT * 8; i += 256) {            // 512 items, 2/thread
            int nl = i >> 3;
            int c8 = i & 7;
            __half2 h0 = __float2half2_rn(0.f), h1 = h0, h2 = h0, h3 = h0;
            #pragma unroll
            for (int k = 0; k < 8; k++) {
                uint2 e = sow[nl][k];
                __half2 wh = *reinterpret_cast<__half2*>(&e.y);
                uint4 v = vb[(size_t)e.x * (NC / 8) + c8];
                const __half2* hp = (const __half2*)&v;
                h0 = __hfma2(hp[0], wh, h0);
                h1 = __hfma2(hp[1], wh, h1);
                h2 = __hfma2(hp[2], wh, h2);
                h3 = __hfma2(hp[3], wh, h3);
            }
            float2 f0 = __half22float2(h0);
            float2 f1 = __half22float2(h1);
            float2 f2 = __half22float2(h2);
            float2 f3 = __half22float2(h3);
            int c = c8 * 8;
            sout[nl][c + 0] = f0.x; sout[nl][c + 1] = f0.y;
            sout[nl][c + 2] = f1.x; sout[nl][c + 3] = f1.y;
            sout[nl][c + 4] = f2.x; sout[nl][c + 5] = f2.y;
            sout[nl][c + 6] = f3.x; sout[nl][c + 7] = f3.y;
        }
    }
    __syncthreads();

    // Phase D: transpose -> out channels [64,128), float4 stores along N
    {
        float* dsto = out + ((size_t)b * 2 * NC + NC) * NPTS;
        for (int i = tid; i < NC * (DT / 4); i += 256) {     // 1024 float4, 4/thread
            int c = i >> 4, g = i & 15;
            int nl = g * 4;
            float4 v = make_float4(sout[nl][c], sout[nl + 1][c],
                                   sout[nl + 2][c], sout[nl + 3][c]);
            *(float4*)&dsto[(size_t)c * NPTS + n0 + nl] = v;
        }
    }
}

// ---------------- launch (single stream, no host-object creation) ----------------
extern "C" void kernel_launch(void* const* d_in, const int* in_sizes, int n_in,
                              void* d_out, int out_size) {
    const float* fptr[2] = {nullptr, nullptr};
    const float* cptr[2] = {nullptr, nullptr};
    int fi = 0, ci = 0;
    for (int i = 0; i < 4; i++) {
        if (in_sizes[i] == NB * NC * NPTS) { if (fi < 2) fptr[fi++] = (const float*)d_in[i]; }
        else                               { if (ci < 2) cptr[ci++] = (const float*)d_in[i]; }
    }
    const float* x1f = fptr[0];
    const float* x2f = fptr[1];
    const float* x1c = cptr[0];
    const float* x2c = cptr[1];
    float* out = (float*)d_out;

    void* stats_ptr = nullptr;
    cudaGetSymbolAddress(&stats_ptr, g_stats);
    cudaMemsetAsync(stats_ptr, 0, 2 * NB * 4 * sizeof(float));

    k_sum<<<128, 256>>>(x1c, x2c);      // also zeroes g_voxh + g_cnt
    k_maxsq<<<128, 256>>>(x1c, x2c);

    dim3 gv(NPTS / 32, NB);
    k_vox<<<gv, 256>>>(x2f, x2c, x1f, out);

    dim3 gd(NPTS / DT, NB);
    k_devox<<<gd, 256>>>(x1f, x1c, out);
}